// round 14
// baseline (speedup 1.0000x reference)
#include <cuda_runtime.h>
#include <cuda_bf16.h>
#include <cstdint>

// Problem: B=8, S=2048, N=4, D=1024
//   mixed[b,s,i,d] = sum_j h_res[b,s,i,j] * x[b,s,j,d]
//   out = mixed * h_out[b,s,d] + h_post[b,s,i] * x[b,s,i,d]
//
// TWO tokens per CTA, 256 threads, all 10 big 128-bit loads front-batched
// (MLP_p1 = 10). NO shared memory and NO barrier: per-token scalars
// (h_res rows, h_post) are loaded warp-uniformly via __ldg (one sector per
// warp, L1-broadcast), so each warp free-runs from load batch to stores
// without any CTA-wide convergence point.

#define TOKENS (8 * 2048)
#define D_DIM 1024
#define D4 (D_DIM / 4)   // 256

__global__ __launch_bounds__(256)
void stream_mix_kernel2(const float* __restrict__ x,
                        const float* __restrict__ h_res,
                        const float* __restrict__ h_out,
                        const float* __restrict__ h_post,
                        float* __restrict__ out) {
    const int tok0 = blockIdx.x * 2;     // even token
    const int d4   = threadIdx.x;        // 0 .. 255

    // Front-batch ALL big loads for both tokens (10 independent LDG.128).
    const float4* xa =
        reinterpret_cast<const float4*>(x + (size_t)tok0 * 4 * D_DIM);
    const float4* xb = xa + 4 * D4;      // next token's x block

    const float4 a0 = __ldcs(&xa[0 * D4 + d4]);
    const float4 a1 = __ldcs(&xa[1 * D4 + d4]);
    const float4 a2 = __ldcs(&xa[2 * D4 + d4]);
    const float4 a3 = __ldcs(&xa[3 * D4 + d4]);
    const float4 b0 = __ldcs(&xb[0 * D4 + d4]);
    const float4 b1 = __ldcs(&xb[1 * D4 + d4]);
    const float4 b2 = __ldcs(&xb[2 * D4 + d4]);
    const float4 b3 = __ldcs(&xb[3 * D4 + d4]);
    const float4 hoa = __ldcs(
        &reinterpret_cast<const float4*>(h_out + (size_t)tok0 * D_DIM)[d4]);
    const float4 hob = __ldcs(
        &reinterpret_cast<const float4*>(h_out + (size_t)(tok0 + 1) * D_DIM)[d4]);

    // Warp-uniform per-token scalars (L1-broadcast; no smem, no barrier).
    const float4* hra = reinterpret_cast<const float4*>(h_res + (size_t)tok0 * 16);
    const float4* hrb = hra + 4;
    const float4 hpa = __ldg(
        &reinterpret_cast<const float4*>(h_post + (size_t)tok0 * 4)[0]);
    const float4 hpb = __ldg(
        &reinterpret_cast<const float4*>(h_post + (size_t)(tok0 + 1) * 4)[0]);

    float4* oa = reinterpret_cast<float4*>(out + (size_t)tok0 * 4 * D_DIM);
    float4* ob = oa + 4 * D4;

    // ---- Token A ----
    {
        {
            const float4 hr = __ldg(&hra[0]);
            float4 o;
            o.x = (hr.x*a0.x + hr.y*a1.x + hr.z*a2.x + hr.w*a3.x) * hoa.x + hpa.x*a0.x;
            o.y = (hr.x*a0.y + hr.y*a1.y + hr.z*a2.y + hr.w*a3.y) * hoa.y + hpa.x*a0.y;
            o.z = (hr.x*a0.z + hr.y*a1.z + hr.z*a2.z + hr.w*a3.z) * hoa.z + hpa.x*a0.z;
            o.w = (hr.x*a0.w + hr.y*a1.w + hr.z*a2.w + hr.w*a3.w) * hoa.w + hpa.x*a0.w;
            __stcs(&oa[0 * D4 + d4], o);
        }
        {
            const float4 hr = __ldg(&hra[1]);
            float4 o;
            o.x = (hr.x*a0.x + hr.y*a1.x + hr.z*a2.x + hr.w*a3.x) * hoa.x + hpa.y*a1.x;
            o.y = (hr.x*a0.y + hr.y*a1.y + hr.z*a2.y + hr.w*a3.y) * hoa.y + hpa.y*a1.y;
            o.z = (hr.x*a0.z + hr.y*a1.z + hr.z*a2.z + hr.w*a3.z) * hoa.z + hpa.y*a1.z;
            o.w = (hr.x*a0.w + hr.y*a1.w + hr.z*a2.w + hr.w*a3.w) * hoa.w + hpa.y*a1.w;
            __stcs(&oa[1 * D4 + d4], o);
        }
        {
            const float4 hr = __ldg(&hra[2]);
            float4 o;
            o.x = (hr.x*a0.x + hr.y*a1.x + hr.z*a2.x + hr.w*a3.x) * hoa.x + hpa.z*a2.x;
            o.y = (hr.x*a0.y + hr.y*a1.y + hr.z*a2.y + hr.w*a3.y) * hoa.y + hpa.z*a2.y;
            o.z = (hr.x*a0.z + hr.y*a1.z + hr.z*a2.z + hr.w*a3.z) * hoa.z + hpa.z*a2.z;
            o.w = (hr.x*a0.w + hr.y*a1.w + hr.z*a2.w + hr.w*a3.w) * hoa.w + hpa.z*a2.w;
            __stcs(&oa[2 * D4 + d4], o);
        }
        {
            const float4 hr = __ldg(&hra[3]);
            float4 o;
            o.x = (hr.x*a0.x + hr.y*a1.x + hr.z*a2.x + hr.w*a3.x) * hoa.x + hpa.w*a3.x;
            o.y = (hr.x*a0.y + hr.y*a1.y + hr.z*a2.y + hr.w*a3.y) * hoa.y + hpa.w*a3.y;
            o.z = (hr.x*a0.z + hr.y*a1.z + hr.z*a2.z + hr.w*a3.z) * hoa.z + hpa.w*a3.z;
            o.w = (hr.x*a0.w + hr.y*a1.w + hr.z*a2.w + hr.w*a3.w) * hoa.w + hpa.w*a3.w;
            __stcs(&oa[3 * D4 + d4], o);
        }
    }

    // ---- Token B ----
    {
        {
            const float4 hr = __ldg(&hrb[0]);
            float4 o;
            o.x = (hr.x*b0.x + hr.y*b1.x + hr.z*b2.x + hr.w*b3.x) * hob.x + hpb.x*b0.x;
            o.y = (hr.x*b0.y + hr.y*b1.y + hr.z*b2.y + hr.w*b3.y) * hob.y + hpb.x*b0.y;
            o.z = (hr.x*b0.z + hr.y*b1.z + hr.z*b2.z + hr.w*b3.z) * hob.z + hpb.x*b0.z;
            o.w = (hr.x*b0.w + hr.y*b1.w + hr.z*b2.w + hr.w*b3.w) * hob.w + hpb.x*b0.w;
            __stcs(&ob[0 * D4 + d4], o);
        }
        {
            const float4 hr = __ldg(&hrb[1]);
            float4 o;
            o.x = (hr.x*b0.x + hr.y*b1.x + hr.z*b2.x + hr.w*b3.x) * hob.x + hpb.y*b1.x;
            o.y = (hr.x*b0.y + hr.y*b1.y + hr.z*b2.y + hr.w*b3.y) * hob.y + hpb.y*b1.y;
            o.z = (hr.x*b0.z + hr.y*b1.z + hr.z*b2.z + hr.w*b3.z) * hob.z + hpb.y*b1.z;
            o.w = (hr.x*b0.w + hr.y*b1.w + hr.z*b2.w + hr.w*b3.w) * hob.w + hpb.y*b1.w;
            __stcs(&ob[1 * D4 + d4], o);
        }
        {
            const float4 hr = __ldg(&hrb[2]);
            float4 o;
            o.x = (hr.x*b0.x + hr.y*b1.x + hr.z*b2.x + hr.w*b3.x) * hob.x + hpb.z*b2.x;
            o.y = (hr.x*b0.y + hr.y*b1.y + hr.z*b2.y + hr.w*b3.y) * hob.y + hpb.z*b2.y;
            o.z = (hr.x*b0.z + hr.y*b1.z + hr.z*b2.z + hr.w*b3.z) * hob.z + hpb.z*b2.z;
            o.w = (hr.x*b0.w + hr.y*b1.w + hr.z*b2.w + hr.w*b3.w) * hob.w + hpb.z*b2.w;
            __stcs(&ob[2 * D4 + d4], o);
        }
        {
            const float4 hr = __ldg(&hrb[3]);
            float4 o;
            o.x = (hr.x*b0.x + hr.y*b1.x + hr.z*b2.x + hr.w*b3.x) * hob.x + hpb.w*b3.x;
            o.y = (hr.x*b0.y + hr.y*b1.y + hr.z*b2.y + hr.w*b3.y) * hob.y + hpb.w*b3.y;
            o.z = (hr.x*b0.z + hr.y*b1.z + hr.z*b2.z + hr.w*b3.z) * hob.z + hpb.w*b3.z;
            o.w = (hr.x*b0.w + hr.y*b1.w + hr.z*b2.w + hr.w*b3.w) * hob.w + hpb.w*b3.w;
            __stcs(&ob[3 * D4 + d4], o);
        }
    }
}

extern "C" void kernel_launch(void* const* d_in, const int* in_sizes, int n_in,
                              void* d_out, int out_size) {
    const float* x      = (const float*)d_in[0];  // [8,2048,4,1024]
    const float* h_res  = (const float*)d_in[1];  // [8,2048,4,4]
    const float* h_out  = (const float*)d_in[2];  // [8,2048,1024]
    const float* h_post = (const float*)d_in[3];  // [8,2048,4]
    float* out = (float*)d_out;                   // [8,2048,4,1024]

    stream_mix_kernel2<<<TOKENS / 2, 256>>>(x, h_res, h_out, h_post, out);
}

// round 15
// speedup vs baseline: 1.0004x; 1.0004x over previous
#include <cuda_runtime.h>
#include <cuda_bf16.h>
#include <cstdint>

// Problem: B=8, S=2048, N=4, D=1024
//   mixed[b,s,i,d] = sum_j h_res[b,s,i,j] * x[b,s,j,d]
//   out = mixed * h_out[b,s,d] + h_post[b,s,i] * x[b,s,i,d]
//
// FOUR tokens per CTA, 256 threads. All 20 big 128-bit loads front-batched
// (MLP_p1 = 20) — extrapolating the burst-depth lever that gave the only
// measured win (R8: MLP 5->10, +2.5%). No smem / no barrier; per-token
// scalars are warp-uniform __ldg.

#define TOKENS (8 * 2048)
#define D_DIM 1024
#define D4 (D_DIM / 4)   // 256

__global__ __launch_bounds__(256)
void stream_mix_kernel4(const float* __restrict__ x,
                        const float* __restrict__ h_res,
                        const float* __restrict__ h_out,
                        const float* __restrict__ h_post,
                        float* __restrict__ out) {
    const int tok0 = blockIdx.x * 4;     // first of 4 tokens
    const int d4   = threadIdx.x;        // 0 .. 255

    const float4* xbase =
        reinterpret_cast<const float4*>(x + (size_t)tok0 * 4 * D_DIM);
    const float4* hobase =
        reinterpret_cast<const float4*>(h_out + (size_t)tok0 * D_DIM);

    // ---- Front-batch ALL 20 big loads (4 tokens x 4 streams + 4 h_out) ----
    float4 xv[4][4];
    float4 hov[4];
#pragma unroll
    for (int t = 0; t < 4; t++) {
#pragma unroll
        for (int j = 0; j < 4; j++) {
            xv[t][j] = __ldcs(&xbase[(t * 4 + j) * D4 + d4]);
        }
    }
#pragma unroll
    for (int t = 0; t < 4; t++) {
        hov[t] = __ldcs(&hobase[t * D4 + d4]);
    }

    const float4* hrbase = reinterpret_cast<const float4*>(h_res + (size_t)tok0 * 16);
    const float4* hpbase = reinterpret_cast<const float4*>(h_post + (size_t)tok0 * 4);

    float4* obase = reinterpret_cast<float4*>(out + (size_t)tok0 * 4 * D_DIM);

    // ---- Compute + store, token by token (frees x regs progressively) ----
#pragma unroll
    for (int t = 0; t < 4; t++) {
        const float4 hp = __ldg(&hpbase[t]);
        const float hps[4] = {hp.x, hp.y, hp.z, hp.w};
        const float4 ho = hov[t];
#pragma unroll
        for (int i = 0; i < 4; i++) {
            const float4 hr = __ldg(&hrbase[t * 4 + i]);
            const float4 xi = xv[t][i];
            float4 o;
            o.x = (hr.x * xv[t][0].x + hr.y * xv[t][1].x + hr.z * xv[t][2].x + hr.w * xv[t][3].x) * ho.x + hps[i] * xi.x;
            o.y = (hr.x * xv[t][0].y + hr.y * xv[t][1].y + hr.z * xv[t][2].y + hr.w * xv[t][3].y) * ho.y + hps[i] * xi.y;
            o.z = (hr.x * xv[t][0].z + hr.y * xv[t][1].z + hr.z * xv[t][2].z + hr.w * xv[t][3].z) * ho.z + hps[i] * xi.z;
            o.w = (hr.x * xv[t][0].w + hr.y * xv[t][1].w + hr.z * xv[t][2].w + hr.w * xv[t][3].w) * ho.w + hps[i] * xi.w;
            __stcs(&obase[(t * 4 + i) * D4 + d4], o);
        }
    }
}

extern "C" void kernel_launch(void* const* d_in, const int* in_sizes, int n_in,
                              void* d_out, int out_size) {
    const float* x      = (const float*)d_in[0];  // [8,2048,4,1024]
    const float* h_res  = (const float*)d_in[1];  // [8,2048,4,4]
    const float* h_out  = (const float*)d_in[2];  // [8,2048,1024]
    const float* h_post = (const float*)d_in[3];  // [8,2048,4]
    float* out = (float*)d_out;                   // [8,2048,4,1024]

    stream_mix_kernel4<<<TOKENS / 4, 256>>>(x, h_res, h_out, h_post, out);
}

// round 16
// speedup vs baseline: 1.0028x; 1.0025x over previous
#include <cuda_runtime.h>
#include <cuda_bf16.h>
#include <cstdint>

// Problem: B=8, S=2048, N=4, D=1024
//   mixed[b,s,i,d] = sum_j h_res[b,s,i,j] * x[b,s,j,d]
//   out = mixed * h_out[b,s,d] + h_post[b,s,i] * x[b,s,i,d]
//
// 256-bit (v8.f32) global loads/stores — sm_100+ PTX. Two tokens per CTA,
// 256 threads: threads [0,128) handle token A, [128,256) token B. Each
// thread owns an 8-float chunk of D (D/8 = 128 chunks). 5 front-batched
// 256-bit loads per thread (4 streams + h_out), 4x 256-bit stores.
// Warp requests are 1KB contiguous per instruction (vs 512B with float4),
// halving request count into L1tex/LTS and lengthening HBM bursts.

#define TOKENS (8 * 2048)
#define D_DIM 1024
#define D8 (D_DIM / 8)   // 128 chunks of 8 floats

struct F8 { float v[8]; };

__device__ __forceinline__ F8 ldg256(const float* p) {
    F8 r;
    asm volatile(
        "ld.global.v8.f32 {%0,%1,%2,%3,%4,%5,%6,%7}, [%8];"
        : "=f"(r.v[0]), "=f"(r.v[1]), "=f"(r.v[2]), "=f"(r.v[3]),
          "=f"(r.v[4]), "=f"(r.v[5]), "=f"(r.v[6]), "=f"(r.v[7])
        : "l"(p));
    return r;
}

__device__ __forceinline__ void stg256(float* p, const F8& r) {
    asm volatile(
        "st.global.v8.f32 [%0], {%1,%2,%3,%4,%5,%6,%7,%8};"
        :: "l"(p),
           "f"(r.v[0]), "f"(r.v[1]), "f"(r.v[2]), "f"(r.v[3]),
           "f"(r.v[4]), "f"(r.v[5]), "f"(r.v[6]), "f"(r.v[7])
        : "memory");
}

__global__ __launch_bounds__(256)
void stream_mix_v8(const float* __restrict__ x,
                   const float* __restrict__ h_res,
                   const float* __restrict__ h_out,
                   const float* __restrict__ h_post,
                   float* __restrict__ out) {
    const int tid = threadIdx.x;
    const int t   = tid >> 7;                 // which of the 2 tokens (0/1)
    const int c   = tid & 127;                // chunk index within D (0..127)
    const int tok = blockIdx.x * 2 + t;

    const float* xb  = x     + (size_t)tok * 4 * D_DIM + c * 8;
    const float* hob = h_out + (size_t)tok * D_DIM     + c * 8;
    float*       ob  = out   + (size_t)tok * 4 * D_DIM + c * 8;

    // Front-batch all 5 independent 256-bit loads.
    const F8 x0 = ldg256(xb + 0 * D_DIM);
    const F8 x1 = ldg256(xb + 1 * D_DIM);
    const F8 x2 = ldg256(xb + 2 * D_DIM);
    const F8 x3 = ldg256(xb + 3 * D_DIM);
    const F8 ho = ldg256(hob);

    // Warp-uniform per-token scalars (L1-broadcast).
    const float4* hrb = reinterpret_cast<const float4*>(h_res + (size_t)tok * 16);
    const float4 hr0 = __ldg(&hrb[0]);
    const float4 hr1 = __ldg(&hrb[1]);
    const float4 hr2 = __ldg(&hrb[2]);
    const float4 hr3 = __ldg(&hrb[3]);
    const float4 hp  = __ldg(
        &reinterpret_cast<const float4*>(h_post + (size_t)tok * 4)[0]);

    F8 o;
    // Stream 0
#pragma unroll
    for (int k = 0; k < 8; k++)
        o.v[k] = (hr0.x * x0.v[k] + hr0.y * x1.v[k] + hr0.z * x2.v[k] + hr0.w * x3.v[k]) * ho.v[k]
                 + hp.x * x0.v[k];
    stg256(ob + 0 * D_DIM, o);
    // Stream 1
#pragma unroll
    for (int k = 0; k < 8; k++)
        o.v[k] = (hr1.x * x0.v[k] + hr1.y * x1.v[k] + hr1.z * x2.v[k] + hr1.w * x3.v[k]) * ho.v[k]
                 + hp.y * x1.v[k];
    stg256(ob + 1 * D_DIM, o);
    // Stream 2
#pragma unroll
    for (int k = 0; k < 8; k++)
        o.v[k] = (hr2.x * x0.v[k] + hr2.y * x1.v[k] + hr2.z * x2.v[k] + hr2.w * x3.v[k]) * ho.v[k]
                 + hp.z * x2.v[k];
    stg256(ob + 2 * D_DIM, o);
    // Stream 3
#pragma unroll
    for (int k = 0; k < 8; k++)
        o.v[k] = (hr3.x * x0.v[k] + hr3.y * x1.v[k] + hr3.z * x2.v[k] + hr3.w * x3.v[k]) * ho.v[k]
                 + hp.w * x3.v[k];
    stg256(ob + 3 * D_DIM, o);
}

extern "C" void kernel_launch(void* const* d_in, const int* in_sizes, int n_in,
                              void* d_out, int out_size) {
    const float* x      = (const float*)d_in[0];  // [8,2048,4,1024]
    const float* h_res  = (const float*)d_in[1];  // [8,2048,4,4]
    const float* h_out  = (const float*)d_in[2];  // [8,2048,1024]
    const float* h_post = (const float*)d_in[3];  // [8,2048,4]
    float* out = (float*)d_out;                   // [8,2048,4,1024]

    stream_mix_v8<<<TOKENS / 2, 256>>>(x, h_res, h_out, h_post, out);
}